// round 9
// baseline (speedup 1.0000x reference)
#include <cuda_runtime.h>
#include <cuda_fp16.h>
#include <cstdint>
#include <math.h>

#define Bz     4
#define Nq     4097
#define CDIM   384
#define HEADS  8
#define HD     48
#define Msr    513
#define KEYPAD 576
#define MPAD   16512        // padded query rows (mult of 128)
#define MRPAD  2176         // padded reduced rows (mult of 128)

// ---------------- scratch (static device globals; zero-init, no allocs) -----
__device__ __half g_xh[(size_t)MPAD * CDIM];            // x fp16
__device__ __half g_qh[(size_t)MPAD * CDIM];            // q (scale*log2e folded)
__device__ __half g_ah[(size_t)MPAD * CDIM];            // attention out fp16
__device__ __half g_xr[(size_t)MRPAD * CDIM];           // reduced+LN tokens
__device__ __half g_kh[(size_t)Bz * KEYPAD * CDIM];     // K fp16, key-padded
__device__ __half g_vt[(size_t)Bz * HEADS * HD * KEYPAD]; // V^T fp16
__device__ __half g_wh[589824];                         // q_w*sc | kv_w | proj_w

// ---------------- helpers ----------------------------------------------------
__device__ __forceinline__ unsigned packh2(float x, float y) {
    __half2 h = __floats2half2_rn(x, y);
    return *(unsigned*)&h;
}
__device__ __forceinline__ void mma_f16(float* d, const unsigned* a,
                                        unsigned b0, unsigned b1) {
    asm volatile(
        "mma.sync.aligned.m16n8k16.row.col.f32.f16.f16.f32 "
        "{%0,%1,%2,%3}, {%4,%5,%6,%7}, {%8,%9}, {%0,%1,%2,%3};"
        : "+f"(d[0]), "+f"(d[1]), "+f"(d[2]), "+f"(d[3])
        : "r"(a[0]), "r"(a[1]), "r"(a[2]), "r"(a[3]), "r"(b0), "r"(b1));
}
__device__ __forceinline__ void ldsm4(unsigned& r0, unsigned& r1,
                                      unsigned& r2, unsigned& r3, unsigned addr) {
    asm volatile("ldmatrix.sync.aligned.m8n8.x4.shared.b16 {%0,%1,%2,%3}, [%4];"
                 : "=r"(r0), "=r"(r1), "=r"(r2), "=r"(r3) : "r"(addr));
}
__device__ __forceinline__ void cp16(unsigned s, const void* g) {
    asm volatile("cp.async.cg.shared.global [%0], [%1], 16;" :: "r"(s), "l"(g));
}
#define CPCOMMIT() asm volatile("cp.async.commit_group;" ::: "memory")
template<int N>
__device__ __forceinline__ void cpwait() {
    asm volatile("cp.async.wait_group %0;" :: "n"(N) : "memory");
}

// ---------------- merged fp32 -> fp16 conversion -----------------------------
#define XC4 ((Bz * Nq * CDIM) / 4)
#define QC4 36864
#define KC4 73728
#define PC4 36864
__global__ __launch_bounds__(256)
void cvt_all(const float* __restrict__ x, const float* __restrict__ qw,
             const float* __restrict__ kvw, const float* __restrict__ pw) {
    int j = blockIdx.x * 256 + threadIdx.x;
    const float* s; __half* d;
    float sc = 1.f;
    if (j < XC4) { s = x; d = g_xh; }
    else {
        j -= XC4;
        if (j < QC4) { s = qw; d = g_wh;
                       sc = 0.14433756729740644f * 1.4426950408889634f; }
        else {
            j -= QC4;
            if (j < KC4) { s = kvw; d = g_wh + 147456; }
            else { j -= KC4; if (j >= PC4) return; s = pw; d = g_wh + 442368; }
        }
    }
    float4 v = *(const float4*)&s[(size_t)j * 4];
    uint2 u = make_uint2(packh2(v.x * sc, v.y * sc), packh2(v.z * sc, v.w * sc));
    *(uint2*)&d[(size_t)j * 4] = u;
}

// ---------------- fused depthwise-conv(2x2x2,s2) + CLS + LayerNorm ----------
__global__ __launch_bounds__(384)
void reduce_ln_kernel(const float* __restrict__ x,
                      const float* __restrict__ sr_w,
                      const float* __restrict__ sr_b,
                      const float* __restrict__ ln_g,
                      const float* __restrict__ ln_b) {
    int m = blockIdx.x, b = blockIdx.y, c = threadIdx.x;
    float val;
    if (m == 0) {
        val = x[(size_t)(b * Nq) * CDIM + c];
    } else {
        int p  = m - 1;
        int z0 = p >> 6, z1 = (p >> 3) & 7, z2 = p & 7;
        int base = 1 + (2 * z0) * 256 + (2 * z1) * 16 + (2 * z2);
        float acc = sr_b[c];
#pragma unroll
        for (int i = 0; i < 2; i++)
#pragma unroll
            for (int j = 0; j < 2; j++)
#pragma unroll
                for (int k = 0; k < 2; k++) {
                    int tok = base + i * 256 + j * 16 + k;
                    acc = fmaf(x[(size_t)(b * Nq + tok) * CDIM + c],
                               sr_w[c * 8 + i * 4 + j * 2 + k], acc);
                }
        val = acc;
    }
    __shared__ float s_sum[12], s_sq[12];
    float v1 = val, v2 = val * val;
#pragma unroll
    for (int off = 16; off > 0; off >>= 1) {
        v1 += __shfl_xor_sync(0xffffffffu, v1, off);
        v2 += __shfl_xor_sync(0xffffffffu, v2, off);
    }
    int warp = c >> 5, lane = c & 31;
    if (lane == 0) { s_sum[warp] = v1; s_sq[warp] = v2; }
    __syncthreads();
    float tot = 0.f, totsq = 0.f;
#pragma unroll
    for (int w = 0; w < 12; w++) { tot += s_sum[w]; totsq += s_sq[w]; }
    float mu  = tot * (1.0f / CDIM);
    float var = totsq * (1.0f / CDIM) - mu * mu;
    float y = (val - mu) * rsqrtf(var + 1e-5f) * ln_g[c] + ln_b[c];
    g_xr[(size_t)(b * Msr + m) * CDIM + c] = __float2half_rn(y);
}

// ---------------- fp16 TC GEMM, BM=128 BN=128 BK=32, 512 threads ------------
// 16 warps in 4x4 grid, 32x32 warp tiles; 3-stage cp.async; ldmatrix
// MODE 0: KV epilogue   MODE 1: fp16 out   MODE 2: fp32 + bias
#define GK     384
#define GSTR   40
#define GSTAGE (256 * GSTR)     // halves per stage
#define NKIT   12
template<int MODE>
__global__ __launch_bounds__(512)
void gemm_h(const __half* __restrict__ A, const __half* __restrict__ W,
            const float* __restrict__ bias, void* __restrict__ Cout,
            int Md, int Nd) {
    extern __shared__ __half sh[];
    int tid = threadIdx.x;
    int warp = tid >> 5, lane = tid & 31;
    int g = lane >> 2, t = lane & 3;
    int wm = warp >> 2, wn = warp & 3;
    int m0 = blockIdx.y * 128, n0 = blockIdx.x * 128;

    unsigned smbase = (unsigned)__cvta_generic_to_shared(sh);
    int li = lane & 7, seg = lane >> 3;
    int a_row = (seg & 1) * 8 + li, a_k = (seg >> 1) * 8;
    int b_row = (seg >> 1) * 8 + li, b_k = (seg & 1) * 8;

    auto issue = [&](int kk, int s) {
        unsigned sb = smbase + s * (GSTAGE * 2);
#pragma unroll
        for (int i = 0; i < 2; i++) {
            int idx = tid + i * 512;              // 0..1023: 16B copies
            int row = idx >> 2, c8 = (idx & 3) * 8;   // 256 rows x 32 halves
            if (row < 128)
                cp16(sb + (row * GSTR + c8) * 2,
                     A + (size_t)(m0 + row) * GK + kk * 32 + c8);
            else
                cp16(sb + (row * GSTR + c8) * 2,
                     W + (size_t)(n0 + row - 128) * GK + kk * 32 + c8);
        }
    };

    float acc[2][4][4] = {};
    issue(0, 0); CPCOMMIT();
    issue(1, 1); CPCOMMIT();

    for (int k = 0; k < NKIT; k++) {
        if (k < NKIT - 1) cpwait<1>(); else cpwait<0>();
        __syncthreads();
        if (k + 2 < NKIT) { issue(k + 2, (k + 2) % 3); CPCOMMIT(); }
        unsigned sb = smbase + (k % 3) * (GSTAGE * 2);
#pragma unroll
        for (int kb = 0; kb < 2; kb++) {
            unsigned a[2][4];
#pragma unroll
            for (int mf = 0; mf < 2; mf++)
                ldsm4(a[mf][0], a[mf][1], a[mf][2], a[mf][3],
                      sb + ((wm * 32 + mf * 16 + a_row) * GSTR + kb * 16 + a_k) * 2);
#pragma unroll
            for (int np = 0; np < 2; np++) {
                unsigned b0, b1, b2, b3;
                ldsm4(b0, b1, b2, b3,
                      sb + ((128 + wn * 32 + np * 16 + b_row) * GSTR + kb * 16 + b_k) * 2);
#pragma unroll
                for (int mf = 0; mf < 2; mf++) {
                    mma_f16(acc[mf][2 * np], a[mf], b0, b1);
                    mma_f16(acc[mf][2 * np + 1], a[mf], b2, b3);
                }
            }
        }
    }

#pragma unroll
    for (int mf = 0; mf < 2; mf++) {
#pragma unroll
        for (int nb = 0; nb < 4; nb++) {
            int col = n0 + wn * 32 + nb * 8 + 2 * t;
            int r = m0 + wm * 32 + mf * 16 + g;
            float* ac = acc[mf][nb];
            if (MODE == 2) {
                float* C = (float*)Cout;
                float bx = bias[col], by = bias[col + 1];
                if (r < Md)
                    *(float2*)&C[(size_t)r * Nd + col] =
                        make_float2(ac[0] + bx, ac[1] + by);
                if (r + 8 < Md)
                    *(float2*)&C[(size_t)(r + 8) * Nd + col] =
                        make_float2(ac[2] + bx, ac[3] + by);
            } else if (MODE == 1) {
                __half* C = (__half*)Cout;
                if (r < Md)
                    *(unsigned*)&C[(size_t)r * Nd + col] = packh2(ac[0], ac[1]);
                if (r + 8 < Md)
                    *(unsigned*)&C[(size_t)(r + 8) * Nd + col] = packh2(ac[2], ac[3]);
            } else {
                if (col < CDIM) {   // K -> key-padded rows
                    if (r < Md) {
                        int bb = r / Msr, key = r % Msr;
                        *(unsigned*)&g_kh[(size_t)(bb * KEYPAD + key) * CDIM + col] =
                            packh2(ac[0], ac[1]);
                    }
                    if (r + 8 < Md) {
                        int bb = (r + 8) / Msr, key = (r + 8) % Msr;
                        *(unsigned*)&g_kh[(size_t)(bb * KEYPAD + key) * CDIM + col] =
                            packh2(ac[2], ac[3]);
                    }
                } else {            // V -> transposed scatter
#pragma unroll
                    for (int e = 0; e < 4; e++) {
                        int rr = r + (e >= 2 ? 8 : 0);
                        if (rr >= Md) continue;
                        int cc = col + (e & 1);
                        int dall = cc - CDIM;
                        int hh = dall / HD, dd = dall % HD;
                        int bb = rr / Msr, key = rr % Msr;
                        g_vt[(((size_t)(bb * HEADS + hh) * HD) + dd) * KEYPAD + key] =
                            __float2half_rn(ac[e]);
                    }
                }
            }
        }
    }
}

// ---------------- fp16 TC flash attention ------------------------------------
// no-max softmax via h2exp2; row-sums via ones-row appended to V^T (col 48)
#define NCHUNK 9
#define KSTRH  56
#define VSTRH  72
#define KSZ    (64 * KSTRH)
#define VSZ    (64 * VSTRH)     // 64 d-rows: 0-47 = V, 48 = ones, 49-63 = zero
__global__ __launch_bounds__(256)
void attn_h_kernel() {
    __shared__ __half ks[3][KSZ];
    __shared__ __half vt[3][VSZ];

    int tid = threadIdx.x;
    int warp = tid >> 5, lane = tid & 31;
    int g = lane >> 2, t = lane & 3;
    int li = lane & 7, seg = lane >> 3;
    int b_row = (seg >> 1) * 8 + li, b_k = (seg & 1) * 8;
    int h = blockIdx.y, b = blockIdx.z;
    int qbase = blockIdx.x * 128 + warp * 16;
    int r0 = qbase + g, r1 = r0 + 8;

    // init ones/zero rows (48..63) of all 3 V stages once
    for (int u = tid; u < 3 * 16 * VSTRH; u += 256) {
        int st = u / (16 * VSTRH);
        int rem = u % (16 * VSTRH);
        int row = 48 + rem / VSTRH, colh = rem % VSTRH;
        vt[st][row * VSTRH + colh] = __float2half(row == 48 ? 1.f : 0.f);
    }
    __syncthreads();

    const __half* kbase = g_kh + (size_t)(b * KEYPAD) * CDIM + h * HD;
    const __half* vbase = g_vt + ((size_t)(b * HEADS + h) * HD) * KEYPAD;
    unsigned ksb = (unsigned)__cvta_generic_to_shared(&ks[0][0]);
    unsigned vtb = (unsigned)__cvta_generic_to_shared(&vt[0][0]);

    auto issue = [&](int c, int s) {
        const __half* kg = kbase + (size_t)c * 64 * CDIM;
        const __half* vg = vbase + c * 64;
        unsigned ku = ksb + s * (KSZ * 2);
        unsigned vu = vtb + s * (VSZ * 2);
#pragma unroll
        for (int i = 0; i < 3; i++) {
            int idx = tid + i * 256;
            if (idx < 384) {
                int key = idx / 6, c8 = (idx % 6) * 8;
                cp16(ku + (key * KSTRH + c8) * 2, kg + (size_t)key * CDIM + c8);
            } else {
                int j = idx - 384, d = j >> 3, c8 = (j & 7) * 8;   // d < 48
                cp16(vu + (d * VSTRH + c8) * 2, vg + (size_t)d * KEYPAD + c8);
            }
        }
    };

    // Q fragments (scale*log2e pre-folded)
    unsigned qf[3][4];
    const __half* qp = g_qh + (size_t)(b * Nq) * CDIM + h * HD;
#pragma unroll
    for (int kb = 0; kb < 3; kb++) {
        int c0 = kb * 16 + 2 * t;
        qf[kb][0] = (r0 < Nq) ? *(const unsigned*)&qp[(size_t)r0 * CDIM + c0] : 0u;
        qf[kb][1] = (r1 < Nq) ? *(const unsigned*)&qp[(size_t)r1 * CDIM + c0] : 0u;
        qf[kb][2] = (r0 < Nq) ? *(const unsigned*)&qp[(size_t)r0 * CDIM + c0 + 8] : 0u;
        qf[kb][3] = (r1 < Nq) ? *(const unsigned*)&qp[(size_t)r1 * CDIM + c0 + 8] : 0u;
    }

    float o[8][4] = {};     // o[0..5]: cols 0-47; o[6][0]/[2] col 48 = row sums

    issue(0, 0); CPCOMMIT();
    issue(1, 1); CPCOMMIT();

    for (int c = 0; c < NCHUNK; c++) {
        if (c < NCHUNK - 1) cpwait<1>(); else cpwait<0>();
        __syncthreads();
        if (c + 2 < NCHUNK) { issue(c + 2, (c + 2) % 3); CPCOMMIT(); }
        int s = c % 3;
        unsigned ku = ksb + s * (KSZ * 2);
        unsigned vu = vtb + s * (VSZ * 2);

        // S = Q @ K^T (12 ldmatrix.x4 + 24 mma)
        float sv[8][4] = {};
#pragma unroll
        for (int kb = 0; kb < 3; kb++) {
#pragma unroll
            for (int np = 0; np < 4; np++) {
                unsigned b0, b1, b2, b3;
                ldsm4(b0, b1, b2, b3,
                      ku + ((np * 16 + b_row) * KSTRH + kb * 16 + b_k) * 2);
                mma_f16(sv[2 * np], qf[kb], b0, b1);
                mma_f16(sv[2 * np + 1], qf[kb], b2, b3);
            }
        }

        if (c == NCHUNK - 1) {      // mask pad keys (only last chunk)
#pragma unroll
            for (int nb = 0; nb < 8; nb++) {
                int key = 512 + nb * 8 + 2 * t;
                if (key >= Msr)     sv[nb][0] = sv[nb][2] = -1e30f;
                if (key + 1 >= Msr) sv[nb][1] = sv[nb][3] = -1e30f;
            }
        }

        // P = 2^S packed in fp16 (h2exp2 halves MUFU traffic)
        unsigned ph01[8], ph23[8];
#pragma unroll
        for (int nb = 0; nb < 8; nb++) {
            __half2 s01 = __floats2half2_rn(sv[nb][0], sv[nb][1]);
            __half2 s23 = __floats2half2_rn(sv[nb][2], sv[nb][3]);
            __half2 p01 = h2exp2(s01);
            __half2 p23 = h2exp2(s23);
            ph01[nb] = *(unsigned*)&p01;
            ph23[nb] = *(unsigned*)&p23;
        }

        // O += P @ [V ; ones] (16 ldmatrix.x4 + 32 mma; col 48 = row sums)
#pragma unroll
        for (int kb = 0; kb < 4; kb++) {
            unsigned a[4] = {ph01[2 * kb], ph23[2 * kb],
                             ph01[2 * kb + 1], ph23[2 * kb + 1]};
#pragma unroll
            for (int np = 0; np < 4; np++) {
                unsigned b0, b1, b2, b3;
                ldsm4(b0, b1, b2, b3,
                      vu + ((np * 16 + b_row) * VSTRH + kb * 16 + b_k) * 2);
                mma_f16(o[2 * np], a, b0, b1);
                mma_f16(o[2 * np + 1], a, b2, b3);
            }
        }
    }

    // row sums live in col 48 (t=0 lanes); broadcast across each quad
    float l0 = __shfl_sync(0xffffffffu, o[6][0], lane & ~3);
    float l1 = __shfl_sync(0xffffffffu, o[6][2], lane & ~3);

    float i0 = 1.f / l0, i1 = 1.f / l1;
    __half* op = g_ah + (size_t)(b * Nq) * CDIM + h * HD;
#pragma unroll
    for (int nb = 0; nb < 6; nb++) {
        int col = nb * 8 + 2 * t;
        if (r0 < Nq)
            *(unsigned*)&op[(size_t)r0 * CDIM + col] = packh2(o[nb][0] * i0, o[nb][1] * i0);
        if (r1 < Nq)
            *(unsigned*)&op[(size_t)r1 * CDIM + col] = packh2(o[nb][2] * i1, o[nb][3] * i1);
    }
}

// ---------------- launcher ---------------------------------------------------
extern "C" void kernel_launch(void* const* d_in, const int* in_sizes, int n_in,
                              void* d_out, int out_size) {
    const float* x      = (const float*)d_in[0];
    const float* q_w    = (const float*)d_in[1];
    const float* kv_w   = (const float*)d_in[2];
    const float* proj_w = (const float*)d_in[3];
    const float* proj_b = (const float*)d_in[4];
    const float* sr_w   = (const float*)d_in[5];
    const float* sr_b   = (const float*)d_in[6];
    const float* ln_g   = (const float*)d_in[7];
    const float* ln_b   = (const float*)d_in[8];
    float* out = (float*)d_out;

    __half *xh, *qh, *ah, *xr, *wh;
    cudaGetSymbolAddress((void**)&xh, g_xh);
    cudaGetSymbolAddress((void**)&qh, g_qh);
    cudaGetSymbolAddress((void**)&ah, g_ah);
    cudaGetSymbolAddress((void**)&xr, g_xr);
    cudaGetSymbolAddress((void**)&wh, g_wh);

    const int Mq = Bz * Nq;        // 16388
    const int Mr = Bz * Msr;       // 2052
    const int CV = XC4 + QC4 + KC4 + PC4;
    const int gsmem = 3 * GSTAGE * 2;   // 61440 B

    cudaFuncSetAttribute(gemm_h<0>, cudaFuncAttributeMaxDynamicSharedMemorySize, gsmem);
    cudaFuncSetAttribute(gemm_h<1>, cudaFuncAttributeMaxDynamicSharedMemorySize, gsmem);
    cudaFuncSetAttribute(gemm_h<2>, cudaFuncAttributeMaxDynamicSharedMemorySize, gsmem);

    // 0. one merged fp32->fp16 conversion pass
    cvt_all<<<(CV + 255) / 256, 256>>>(x, q_w, kv_w, proj_w);
    // 1. reduced tokens + LN (fp16 out)
    reduce_ln_kernel<<<dim3(Msr, Bz), 384>>>(x, sr_w, sr_b, ln_g, ln_b);
    // 2. kv projection -> key-padded K + V^T scatter
    gemm_h<0><<<dim3(768 / 128, (Mr + 127) / 128), 512, gsmem>>>(
        xr, wh + 147456, nullptr, nullptr, Mr, 2 * CDIM);
    // 3. q projection
    gemm_h<1><<<dim3(CDIM / 128, (Mq + 127) / 128), 512, gsmem>>>(
        xh, wh, nullptr, qh, Mq, CDIM);
    // 4. attention
    attn_h_kernel<<<dim3((Nq + 127) / 128, HEADS, Bz), 256>>>();
    // 5. output projection + bias (fp32 out)
    gemm_h<2><<<dim3(CDIM / 128, (Mq + 127) / 128), 512, gsmem>>>(
        ah, wh + 442368, proj_b, out, Mq, CDIM);
}

// round 12
// speedup vs baseline: 1.1343x; 1.1343x over previous
#include <cuda_runtime.h>
#include <cuda_fp16.h>
#include <cstdint>
#include <math.h>

#define Bz     4
#define Nq     4097
#define CDIM   384
#define HEADS  8
#define HD     48
#define Msr    513
#define KEYPAD 528          // 512 full-chunk keys + 16-key tail
#define MPAD   16512        // padded query rows (mult of 128)
#define MRPAD  2176         // padded reduced rows (mult of 128)

// ---------------- scratch (static device globals; zero-init, no allocs) -----
__device__ __half g_xh[(size_t)MPAD * CDIM];            // x fp16
__device__ __half g_qh[(size_t)MPAD * CDIM];            // q (scale*log2e folded)
__device__ __half g_ah[(size_t)MPAD * CDIM];            // attention out fp16
__device__ __half g_xr[(size_t)MRPAD * CDIM];           // reduced+LN tokens
__device__ __half g_kh[(size_t)Bz * KEYPAD * CDIM];     // K fp16, key-padded
__device__ __half g_vt[(size_t)Bz * HEADS * HD * KEYPAD]; // V^T fp16
__device__ __half g_wh[589824];                         // q_w*sc | kv_w | proj_w

// ---------------- helpers ----------------------------------------------------
__device__ __forceinline__ unsigned packh2(float x, float y) {
    __half2 h = __floats2half2_rn(x, y);
    return *(unsigned*)&h;
}
__device__ __forceinline__ float ex2(float x) {
    float y;
    asm("ex2.approx.ftz.f32 %0, %1;" : "=f"(y) : "f"(x));
    return y;
}
__device__ __forceinline__ void mma_f16(float* d, const unsigned* a,
                                        unsigned b0, unsigned b1) {
    asm volatile(
        "mma.sync.aligned.m16n8k16.row.col.f32.f16.f16.f32 "
        "{%0,%1,%2,%3}, {%4,%5,%6,%7}, {%8,%9}, {%0,%1,%2,%3};"
        : "+f"(d[0]), "+f"(d[1]), "+f"(d[2]), "+f"(d[3])
        : "r"(a[0]), "r"(a[1]), "r"(a[2]), "r"(a[3]), "r"(b0), "r"(b1));
}
__device__ __forceinline__ void ldsm4(unsigned& r0, unsigned& r1,
                                      unsigned& r2, unsigned& r3, unsigned addr) {
    asm volatile("ldmatrix.sync.aligned.m8n8.x4.shared.b16 {%0,%1,%2,%3}, [%4];"
                 : "=r"(r0), "=r"(r1), "=r"(r2), "=r"(r3) : "r"(addr));
}
__device__ __forceinline__ void cp16(unsigned s, const void* g) {
    asm volatile("cp.async.cg.shared.global [%0], [%1], 16;" :: "r"(s), "l"(g));
}
#define CPCOMMIT() asm volatile("cp.async.commit_group;" ::: "memory")
template<int N>
__device__ __forceinline__ void cpwait() {
    asm volatile("cp.async.wait_group %0;" :: "n"(N) : "memory");
}
__device__ __forceinline__ unsigned smem_u32(const void* p) {
    return (unsigned)__cvta_generic_to_shared(p);
}

// ---------------- merged fp32 -> fp16 conversion -----------------------------
#define XC4 ((Bz * Nq * CDIM) / 4)
#define QC4 36864
#define KC4 73728
#define PC4 36864
__global__ __launch_bounds__(256)
void cvt_all(const float* __restrict__ x, const float* __restrict__ qw,
             const float* __restrict__ kvw, const float* __restrict__ pw) {
    int j = blockIdx.x * 256 + threadIdx.x;
    const float* s; __half* d;
    float sc = 1.f;
    if (j < XC4) { s = x; d = g_xh; }
    else {
        j -= XC4;
        if (j < QC4) { s = qw; d = g_wh;
                       sc = 0.14433756729740644f * 1.4426950408889634f; }
        else {
            j -= QC4;
            if (j < KC4) { s = kvw; d = g_wh + 147456; }
            else { j -= KC4; if (j >= PC4) return; s = pw; d = g_wh + 442368; }
        }
    }
    float4 v = *(const float4*)&s[(size_t)j * 4];
    uint2 u = make_uint2(packh2(v.x * sc, v.y * sc), packh2(v.z * sc, v.w * sc));
    *(uint2*)&d[(size_t)j * 4] = u;
}

// ---------------- fused depthwise-conv(2x2x2,s2) + CLS + LayerNorm ----------
__global__ __launch_bounds__(384)
void reduce_ln_kernel(const float* __restrict__ x,
                      const float* __restrict__ sr_w,
                      const float* __restrict__ sr_b,
                      const float* __restrict__ ln_g,
                      const float* __restrict__ ln_b) {
    int m = blockIdx.x, b = blockIdx.y, c = threadIdx.x;
    float val;
    if (m == 0) {
        val = x[(size_t)(b * Nq) * CDIM + c];
    } else {
        int p  = m - 1;
        int z0 = p >> 6, z1 = (p >> 3) & 7, z2 = p & 7;
        int base = 1 + (2 * z0) * 256 + (2 * z1) * 16 + (2 * z2);
        float acc = sr_b[c];
#pragma unroll
        for (int i = 0; i < 2; i++)
#pragma unroll
            for (int j = 0; j < 2; j++)
#pragma unroll
                for (int k = 0; k < 2; k++) {
                    int tok = base + i * 256 + j * 16 + k;
                    acc = fmaf(x[(size_t)(b * Nq + tok) * CDIM + c],
                               sr_w[c * 8 + i * 4 + j * 2 + k], acc);
                }
        val = acc;
    }
    __shared__ float s_sum[12], s_sq[12];
    float v1 = val, v2 = val * val;
#pragma unroll
    for (int off = 16; off > 0; off >>= 1) {
        v1 += __shfl_xor_sync(0xffffffffu, v1, off);
        v2 += __shfl_xor_sync(0xffffffffu, v2, off);
    }
    int warp = c >> 5, lane = c & 31;
    if (lane == 0) { s_sum[warp] = v1; s_sq[warp] = v2; }
    __syncthreads();
    float tot = 0.f, totsq = 0.f;
#pragma unroll
    for (int w = 0; w < 12; w++) { tot += s_sum[w]; totsq += s_sq[w]; }
    float mu  = tot * (1.0f / CDIM);
    float var = totsq * (1.0f / CDIM) - mu * mu;
    float y = (val - mu) * rsqrtf(var + 1e-5f) * ln_g[c] + ln_b[c];
    g_xr[(size_t)(b * Msr + m) * CDIM + c] = __float2half_rn(y);
}

// ---------------- fp16 TC GEMM, BM=128 BN=128 BK=64, 3-stage, ldmatrix ------
// 8 warps (4 M x 2 N), warp tile 32x64
// MODE 0: KV epilogue   MODE 1: fp16 out   MODE 2: fp32 + bias
#define GK     384
#define GSTR   72
#define GSTAGE (256 * GSTR)     // halves per stage (A 128*72 + W 128*72)
#define NKIT   6
template<int MODE>
__global__ __launch_bounds__(256)
void gemm_h(const __half* __restrict__ A, const __half* __restrict__ W,
            const float* __restrict__ bias, void* __restrict__ Cout,
            int Md, int Nd) {
    extern __shared__ __half sh[];
    int tid = threadIdx.x;
    int warp = tid >> 5, lane = tid & 31;
    int g = lane >> 2, t = lane & 3;
    int wm = warp & 3, wn = warp >> 2;
    int m0 = blockIdx.y * 128, n0 = blockIdx.x * 128;

    unsigned smbase = smem_u32(sh);
    int li = lane & 7, seg = lane >> 3;
    int a_row = (seg & 1) * 8 + li, a_k = (seg >> 1) * 8;
    int b_row = (seg >> 1) * 8 + li, b_k = (seg & 1) * 8;

    auto issue = [&](int kk, int s) {
        unsigned sb = smbase + s * (GSTAGE * 2);
#pragma unroll
        for (int i = 0; i < 8; i++) {
            int idx = tid + i * 256;              // 0..2047 16B copies
            int row = idx >> 3, c8 = (idx & 7) * 8;   // 256 rows x 64 halves
            if (row < 128)
                cp16(sb + (row * GSTR + c8) * 2,
                     A + (size_t)(m0 + row) * GK + kk * 64 + c8);
            else
                cp16(sb + (row * GSTR + c8) * 2,
                     W + (size_t)(n0 + row - 128) * GK + kk * 64 + c8);
        }
    };

    float acc[2][8][4] = {};
    issue(0, 0); CPCOMMIT();
    issue(1, 1); CPCOMMIT();

    for (int k = 0; k < NKIT; k++) {
        if (k < NKIT - 1) cpwait<1>(); else cpwait<0>();
        __syncthreads();
        if (k + 2 < NKIT) { issue(k + 2, (k + 2) % 3); CPCOMMIT(); }
        unsigned sb = smbase + (k % 3) * (GSTAGE * 2);
#pragma unroll
        for (int kb = 0; kb < 4; kb++) {
            unsigned a[2][4];
#pragma unroll
            for (int mf = 0; mf < 2; mf++)
                ldsm4(a[mf][0], a[mf][1], a[mf][2], a[mf][3],
                      smbase + (k % 3) * (GSTAGE * 2) +
                      ((wm * 32 + mf * 16 + a_row) * GSTR + kb * 16 + a_k) * 2);
#pragma unroll
            for (int np = 0; np < 4; np++) {
                unsigned b0, b1, b2, b3;
                ldsm4(b0, b1, b2, b3,
                      sb + ((128 + wn * 64 + np * 16 + b_row) * GSTR + kb * 16 + b_k) * 2);
#pragma unroll
                for (int mf = 0; mf < 2; mf++) {
                    mma_f16(acc[mf][2 * np], a[mf], b0, b1);
                    mma_f16(acc[mf][2 * np + 1], a[mf], b2, b3);
                }
            }
        }
    }

#pragma unroll
    for (int mf = 0; mf < 2; mf++) {
#pragma unroll
        for (int nb = 0; nb < 8; nb++) {
            int col = n0 + wn * 64 + nb * 8 + 2 * t;
            int r = m0 + wm * 32 + mf * 16 + g;
            float* ac = acc[mf][nb];
            if (MODE == 2) {
                float* C = (float*)Cout;
                float bx = bias[col], by = bias[col + 1];
                if (r < Md)
                    *(float2*)&C[(size_t)r * Nd + col] =
                        make_float2(ac[0] + bx, ac[1] + by);
                if (r + 8 < Md)
                    *(float2*)&C[(size_t)(r + 8) * Nd + col] =
                        make_float2(ac[2] + bx, ac[3] + by);
            } else if (MODE == 1) {
                __half* C = (__half*)Cout;
                if (r < Md)
                    *(unsigned*)&C[(size_t)r * Nd + col] = packh2(ac[0], ac[1]);
                if (r + 8 < Md)
                    *(unsigned*)&C[(size_t)(r + 8) * Nd + col] = packh2(ac[2], ac[3]);
            } else {
                if (col < CDIM) {   // K -> key-padded rows
                    if (r < Md) {
                        int bb = r / Msr, key = r % Msr;
                        *(unsigned*)&g_kh[(size_t)(bb * KEYPAD + key) * CDIM + col] =
                            packh2(ac[0], ac[1]);
                    }
                    if (r + 8 < Md) {
                        int bb = (r + 8) / Msr, key = (r + 8) % Msr;
                        *(unsigned*)&g_kh[(size_t)(bb * KEYPAD + key) * CDIM + col] =
                            packh2(ac[2], ac[3]);
                    }
                } else {            // V -> transposed scatter
#pragma unroll
                    for (int e = 0; e < 4; e++) {
                        int rr = r + (e >= 2 ? 8 : 0);
                        if (rr >= Md) continue;
                        int cc = col + (e & 1);
                        int dall = cc - CDIM;
                        int hh = dall / HD, dd = dall % HD;
                        int bb = rr / Msr, key = rr % Msr;
                        g_vt[(((size_t)(bb * HEADS + hh) * HD) + dd) * KEYPAD + key] =
                            __float2half_rn(ac[e]);
                    }
                }
            }
        }
    }
}

// ---------------- fp16 TC flash attention ------------------------------------
// 8 full 64-key chunks (keys 0-511, no masking) + 16-key tail (key 512)
#define KSTRH  56
#define VSTRH  72
#define KSZ    (64 * KSTRH)
#define VSZ    (HD * VSTRH)
__global__ __launch_bounds__(256)
void attn_h_kernel() {
    __shared__ __half ks[3][KSZ];
    __shared__ __half vt[3][VSZ];

    int tid = threadIdx.x;
    int warp = tid >> 5, lane = tid & 31;
    int g = lane >> 2, t = lane & 3;
    int li = lane & 7, seg = lane >> 3;
    int b_row = (seg >> 1) * 8 + li, b_k = (seg & 1) * 8;
    int h = blockIdx.y, b = blockIdx.z;
    int qbase = blockIdx.x * 128 + warp * 16;
    int r0 = qbase + g, r1 = r0 + 8;

    const __half* kbase = g_kh + (size_t)(b * KEYPAD) * CDIM + h * HD;
    const __half* vbase = g_vt + ((size_t)(b * HEADS + h) * HD) * KEYPAD;
    unsigned ksb = smem_u32(&ks[0][0]);
    unsigned vtb = smem_u32(&vt[0][0]);

    auto issue = [&](int c, int s) {
        unsigned ku = ksb + s * (KSZ * 2);
        unsigned vu = vtb + s * (VSZ * 2);
        if (c < 8) {            // full 64-key chunk
            const __half* kg = kbase + (size_t)c * 64 * CDIM;
            const __half* vg = vbase + c * 64;
#pragma unroll
            for (int i = 0; i < 3; i++) {
                int idx = tid + i * 256;
                if (idx < 384) {
                    int key = idx / 6, c8 = (idx % 6) * 8;
                    cp16(ku + (key * KSTRH + c8) * 2, kg + (size_t)key * CDIM + c8);
                } else {
                    int j = idx - 384, d = j >> 3, c8 = (j & 7) * 8;
                    cp16(vu + (d * VSTRH + c8) * 2, vg + (size_t)d * KEYPAD + c8);
                }
            }
        } else {                // 16-key tail (keys 512..527)
            const __half* kg = kbase + (size_t)512 * CDIM;
            const __half* vg = vbase + 512;
            if (tid < 96) {
                int key = tid / 6, c8 = (tid % 6) * 8;
                cp16(ku + (key * KSTRH + c8) * 2, kg + (size_t)key * CDIM + c8);
            } else if (tid < 192) {
                int j = tid - 96, d = j >> 1, c8 = (j & 1) * 8;
                cp16(vu + (d * VSTRH + c8) * 2, vg + (size_t)d * KEYPAD + c8);
            }
        }
    };

    // Q fragments (scale*log2e pre-folded)
    unsigned qf[3][4];
    const __half* qp = g_qh + (size_t)(b * Nq) * CDIM + h * HD;
#pragma unroll
    for (int kb = 0; kb < 3; kb++) {
        int c0 = kb * 16 + 2 * t;
        qf[kb][0] = (r0 < Nq) ? *(const unsigned*)&qp[(size_t)r0 * CDIM + c0] : 0u;
        qf[kb][1] = (r1 < Nq) ? *(const unsigned*)&qp[(size_t)r1 * CDIM + c0] : 0u;
        qf[kb][2] = (r0 < Nq) ? *(const unsigned*)&qp[(size_t)r0 * CDIM + c0 + 8] : 0u;
        qf[kb][3] = (r1 < Nq) ? *(const unsigned*)&qp[(size_t)r1 * CDIM + c0 + 8] : 0u;
    }

    float o[6][4] = {};
    float l0 = 0.f, l1 = 0.f;

    issue(0, 0); CPCOMMIT();
    issue(1, 1); CPCOMMIT();

    for (int c = 0; c <= 8; c++) {
        if (c < 8) cpwait<1>(); else cpwait<0>();
        __syncthreads();
        if (c + 2 <= 8) { issue(c + 2, (c + 2) % 3); CPCOMMIT(); }
        int s = c % 3;
        unsigned ku = ksb + s * (KSZ * 2);
        unsigned vu = vtb + s * (VSZ * 2);

        if (c < 8) {
            // S = Q @ K^T (12 ldmatrix.x4 + 24 mma); all keys valid
            float sv[8][4] = {};
#pragma unroll
            for (int kb = 0; kb < 3; kb++) {
#pragma unroll
                for (int np = 0; np < 4; np++) {
                    unsigned b0, b1, b2, b3;
                    ldsm4(b0, b1, b2, b3,
                          ku + ((np * 16 + b_row) * KSTRH + kb * 16 + b_k) * 2);
                    mma_f16(sv[2 * np], qf[kb], b0, b1);
                    mma_f16(sv[2 * np + 1], qf[kb], b2, b3);
                }
            }

            // P = 2^S
            unsigned ph01[8], ph23[8];
#pragma unroll
            for (int nb = 0; nb < 8; nb++) {
                float p0 = ex2(sv[nb][0]);
                float p1 = ex2(sv[nb][1]);
                float p2 = ex2(sv[nb][2]);
                float p3 = ex2(sv[nb][3]);
                l0 += p0 + p1; l1 += p2 + p3;
                ph01[nb] = packh2(p0, p1);
                ph23[nb] = packh2(p2, p3);
            }

            // O += P @ V (12 ldmatrix.x4 + 24 mma)
#pragma unroll
            for (int kb = 0; kb < 4; kb++) {
                unsigned a[4] = {ph01[2 * kb], ph23[2 * kb],
                                 ph01[2 * kb + 1], ph23[2 * kb + 1]};
#pragma unroll
                for (int np = 0; np < 3; np++) {
                    unsigned b0, b1, b2, b3;
                    ldsm4(b0, b1, b2, b3,
                          vu + ((np * 16 + b_row) * VSTRH + kb * 16 + b_k) * 2);
                    mma_f16(o[2 * np], a, b0, b1);
                    mma_f16(o[2 * np + 1], a, b2, b3);
                }
            }
        } else {
            // 16-key tail: only key 512 (tail index 0) is valid
            float sv0[4] = {}, sv1[4] = {};
#pragma unroll
            for (int kb = 0; kb < 3; kb++) {
                unsigned b0, b1, b2, b3;
                ldsm4(b0, b1, b2, b3,
                      ku + (b_row * KSTRH + kb * 16 + b_k) * 2);
                mma_f16(sv0, qf[kb], b0, b1);
                mma_f16(sv1, qf[kb], b2, b3);
            }
            (void)sv1;
            float p0 = (t == 0) ? ex2(sv0[0]) : 0.f;
            float p2 = (t == 0) ? ex2(sv0[2]) : 0.f;
            l0 += p0; l1 += p2;
            unsigned a[4] = {packh2(p0, 0.f), packh2(p2, 0.f), 0u, 0u};
#pragma unroll
            for (int np = 0; np < 3; np++) {
                unsigned b0, b1, b2, b3;
                ldsm4(b0, b1, b2, b3,
                      vu + ((np * 16 + b_row) * VSTRH + b_k) * 2);
                mma_f16(o[2 * np], a, b0, b1);
                mma_f16(o[2 * np + 1], a, b2, b3);
            }
        }
    }

    l0 += __shfl_xor_sync(0xffffffffu, l0, 1);
    l0 += __shfl_xor_sync(0xffffffffu, l0, 2);
    l1 += __shfl_xor_sync(0xffffffffu, l1, 1);
    l1 += __shfl_xor_sync(0xffffffffu, l1, 2);

    float i0 = 1.f / l0, i1 = 1.f / l1;
    __half* op = g_ah + (size_t)(b * Nq) * CDIM + h * HD;
#pragma unroll
    for (int nb = 0; nb < 6; nb++) {
        int col = nb * 8 + 2 * t;
        if (r0 < Nq)
            *(unsigned*)&op[(size_t)r0 * CDIM + col] = packh2(o[nb][0] * i0, o[nb][1] * i0);
        if (r1 < Nq)
            *(unsigned*)&op[(size_t)r1 * CDIM + col] = packh2(o[nb][2] * i1, o[nb][3] * i1);
    }
}

// ---------------- launcher ---------------------------------------------------
extern "C" void kernel_launch(void* const* d_in, const int* in_sizes, int n_in,
                              void* d_out, int out_size) {
    const float* x      = (const float*)d_in[0];
    const float* q_w    = (const float*)d_in[1];
    const float* kv_w   = (const float*)d_in[2];
    const float* proj_w = (const float*)d_in[3];
    const float* proj_b = (const float*)d_in[4];
    const float* sr_w   = (const float*)d_in[5];
    const float* sr_b   = (const float*)d_in[6];
    const float* ln_g   = (const float*)d_in[7];
    const float* ln_b   = (const float*)d_in[8];
    float* out = (float*)d_out;

    __half *xh, *qh, *ah, *xr, *wh;
    cudaGetSymbolAddress((void**)&xh, g_xh);
    cudaGetSymbolAddress((void**)&qh, g_qh);
    cudaGetSymbolAddress((void**)&ah, g_ah);
    cudaGetSymbolAddress((void**)&xr, g_xr);
    cudaGetSymbolAddress((void**)&wh, g_wh);

    const int Mq = Bz * Nq;        // 16388
    const int Mr = Bz * Msr;       // 2052
    const int CV = XC4 + QC4 + KC4 + PC4;
    const int gsmem = 3 * GSTAGE * 2;   // 110592 B

    cudaFuncSetAttribute(gemm_h<0>, cudaFuncAttributeMaxDynamicSharedMemorySize, gsmem);
    cudaFuncSetAttribute(gemm_h<1>, cudaFuncAttributeMaxDynamicSharedMemorySize, gsmem);
    cudaFuncSetAttribute(gemm_h<2>, cudaFuncAttributeMaxDynamicSharedMemorySize, gsmem);

    // 0. one merged fp32->fp16 conversion pass
    cvt_all<<<(CV + 255) / 256, 256>>>(x, q_w, kv_w, proj_w);
    // 1. reduced tokens + LN (fp16 out)
    reduce_ln_kernel<<<dim3(Msr, Bz), 384>>>(x, sr_w, sr_b, ln_g, ln_b);
    // 2. kv projection -> key-padded K + V^T scatter
    gemm_h<0><<<dim3(768 / 128, (Mr + 127) / 128), 256, gsmem>>>(
        xr, wh + 147456, nullptr, nullptr, Mr, 2 * CDIM);
    // 3. q projection
    gemm_h<1><<<dim3(CDIM / 128, (Mq + 127) / 128), 256, gsmem>>>(
        xh, wh, nullptr, qh, Mq, CDIM);
    // 4. attention
    attn_h_kernel<<<dim3((Nq + 127) / 128, HEADS, Bz), 256>>>();
    // 5. output projection + bias (fp32 out)
    gemm_h<2><<<dim3(CDIM / 128, (Mq + 127) / 128), 256, gsmem>>>(
        ah, wh + 442368, proj_b, out, Mq, CDIM);
}